// round 1
// baseline (speedup 1.0000x reference)
#include <cuda_runtime.h>

#define NB 4096     // anchors
#define ND 256      // dim
#define NL 4        // eps levels
#define NC 2048     // centroids per level
#define NN 100000   // labels per level

#define BM 32       // anchors per block
#define BN 128      // centroids per block tile
#define TK 32       // k-chunk
#define ASTR 36     // padded row stride (floats)
#define BSTR 36

__device__ float g_an[NB * ND];          // normalized anchors   (4 MB)
__device__ float g_cent[NL * NC * ND];   // normalized centroids (8 MB)
__device__ float g_mx[NB * NL];          // per (anchor, l) max over non-pos
__device__ float g_mn[NB * NL];          // per (anchor, l) min over pos

// ---------------------------------------------------------------------------
// Row L2 normalization: one warp per 256-wide row. which==0 -> g_an, 1 -> g_cent
// ---------------------------------------------------------------------------
__global__ void normalize_rows_kernel(const float* __restrict__ in, int rows, int which) {
    int row  = blockIdx.x * 8 + (threadIdx.x >> 5);
    int lane = threadIdx.x & 31;
    if (row >= rows) return;
    float* out = which ? g_cent : g_an;

    const float4* ip = reinterpret_cast<const float4*>(in) + (size_t)row * (ND / 4);
    float4 v0 = ip[lane];
    float4 v1 = ip[lane + 32];
    float ss = v0.x*v0.x + v0.y*v0.y + v0.z*v0.z + v0.w*v0.w
             + v1.x*v1.x + v1.y*v1.y + v1.z*v1.z + v1.w*v1.w;
    #pragma unroll
    for (int o = 16; o > 0; o >>= 1) ss += __shfl_xor_sync(0xffffffffu, ss, o);
    float scale = 1.0f / fmaxf(sqrtf(ss), 1e-12f);

    v0.x *= scale; v0.y *= scale; v0.z *= scale; v0.w *= scale;
    v1.x *= scale; v1.y *= scale; v1.z *= scale; v1.w *= scale;
    float4* op = reinterpret_cast<float4*>(out) + (size_t)row * (ND / 4);
    op[lane]      = v0;
    op[lane + 32] = v1;
}

// ---------------------------------------------------------------------------
// Fused GEMM + masked max/min reduction.
// Block: (anchor tile m0 of 32) x (eps level l). Loops over 16 tiles of 128
// centroids, K double-buffered in chunks of 32. Thread tile 4x8 (128 threads,
// 16x8 logical: tx in [0,16) -> 8 cols each (tx+16j), ty in [0,8) -> 4 rows).
// ---------------------------------------------------------------------------
__global__ void __launch_bounds__(128)
simred_kernel(const int* __restrict__ clab,
              const int* __restrict__ lpe,
              const int* __restrict__ lidx) {
    __shared__ float As[2][BM * ASTR];
    __shared__ float Bs[2][BN * BSTR];
    __shared__ int labA[BM];
    __shared__ int labC[BN];

    const int l   = blockIdx.y;
    const int m0  = blockIdx.x * BM;
    const int tid = threadIdx.x;
    const int tx  = tid & 15;
    const int ty  = tid >> 4;

    if (tid < BM) {
        int li = lidx[m0 + tid];
        labA[tid] = lpe[l * NN + li];
    }
    __syncthreads();

    int myLab[4];
    #pragma unroll
    for (int i = 0; i < 4; i++) myLab[i] = labA[ty * 4 + i];

    float mxv[4] = {-2.f, -2.f, -2.f, -2.f};
    float mnv[4] = { 2.f,  2.f,  2.f,  2.f};

    const float* anp = g_an  + (size_t)m0 * ND;
    const float* cp  = g_cent + (size_t)l * NC * ND;

    for (int n0 = 0; n0 < NC; n0 += BN) {
        labC[tid] = clab[l * NC + n0 + tid];   // BN == blockDim.x == 128

        // prologue: chunk 0 -> buffer 0
        #pragma unroll
        for (int it = 0; it < 2; it++) {               // A: 32x32 = 256 float4
            int q = tid + it * 128;
            int r = q >> 3, k4 = q & 7;
            float4 v = *reinterpret_cast<const float4*>(anp + (size_t)r * ND + k4 * 4);
            *reinterpret_cast<float4*>(&As[0][r * ASTR + k4 * 4]) = v;
        }
        #pragma unroll
        for (int it = 0; it < 8; it++) {               // B: 128x32 = 1024 float4
            int q = tid + it * 128;
            int r = q >> 3, k4 = q & 7;
            float4 v = *reinterpret_cast<const float4*>(cp + (size_t)(n0 + r) * ND + k4 * 4);
            *reinterpret_cast<float4*>(&Bs[0][r * BSTR + k4 * 4]) = v;
        }
        __syncthreads();

        int colLab[8];
        #pragma unroll
        for (int j = 0; j < 8; j++) colLab[j] = labC[tx + 16 * j];

        float acc[4][8];
        #pragma unroll
        for (int i = 0; i < 4; i++)
            #pragma unroll
            for (int j = 0; j < 8; j++) acc[i][j] = 0.f;

        #pragma unroll 1
        for (int kc = 0; kc < ND / TK; kc++) {
            const int cur = kc & 1, nxt = cur ^ 1;
            if (kc + 1 < ND / TK) {
                const int k0 = (kc + 1) * TK;
                #pragma unroll
                for (int it = 0; it < 2; it++) {
                    int q = tid + it * 128;
                    int r = q >> 3, k4 = q & 7;
                    float4 v = *reinterpret_cast<const float4*>(anp + (size_t)r * ND + k0 + k4 * 4);
                    *reinterpret_cast<float4*>(&As[nxt][r * ASTR + k4 * 4]) = v;
                }
                #pragma unroll
                for (int it = 0; it < 8; it++) {
                    int q = tid + it * 128;
                    int r = q >> 3, k4 = q & 7;
                    float4 v = *reinterpret_cast<const float4*>(cp + (size_t)(n0 + r) * ND + k0 + k4 * 4);
                    *reinterpret_cast<float4*>(&Bs[nxt][r * BSTR + k4 * 4]) = v;
                }
            }
            #pragma unroll
            for (int k4 = 0; k4 < TK / 4; k4++) {
                float4 a[4], b[8];
                #pragma unroll
                for (int i = 0; i < 4; i++)
                    a[i] = *reinterpret_cast<const float4*>(&As[cur][(ty * 4 + i) * ASTR + k4 * 4]);
                #pragma unroll
                for (int j = 0; j < 8; j++)
                    b[j] = *reinterpret_cast<const float4*>(&Bs[cur][(tx + 16 * j) * BSTR + k4 * 4]);
                #pragma unroll
                for (int i = 0; i < 4; i++)
                    #pragma unroll
                    for (int j = 0; j < 8; j++) {
                        acc[i][j] += a[i].x * b[j].x;
                        acc[i][j] += a[i].y * b[j].y;
                        acc[i][j] += a[i].z * b[j].z;
                        acc[i][j] += a[i].w * b[j].w;
                    }
            }
            __syncthreads();
        }

        // epilogue: fold tile into running masked max / min (registers only)
        #pragma unroll
        for (int i = 0; i < 4; i++) {
            #pragma unroll
            for (int j = 0; j < 8; j++) {
                float s = acc[i][j];
                bool isp = (myLab[i] >= 0) && (myLab[i] == colLab[j]);
                if (isp) mnv[i] = fminf(mnv[i], s);
                else     mxv[i] = fmaxf(mxv[i], s);
            }
        }
        __syncthreads();   // labC / smem safe to overwrite next tile
    }

    // reduce across the 16 column-threads (tx) sharing each anchor row
    #pragma unroll
    for (int i = 0; i < 4; i++) {
        float mx = mxv[i], mn = mnv[i];
        #pragma unroll
        for (int o = 8; o > 0; o >>= 1) {
            mx = fmaxf(mx, __shfl_xor_sync(0xffffffffu, mx, o));
            mn = fminf(mn, __shfl_xor_sync(0xffffffffu, mn, o));
        }
        if (tx == 0) {
            int b = m0 + ty * 4 + i;
            g_mx[b * NL + l] = mx;
            g_mn[b * NL + l] = mn;
        }
    }
}

// ---------------------------------------------------------------------------
// Final reduction: combine per-(anchor, l) partials -> scalar loss.
// has_neg is always true (<=4 positives among 8192 columns).
// ---------------------------------------------------------------------------
__global__ void finalize_kernel(float* __restrict__ out) {
    __shared__ float s_s[32], s_c[32];
    float sum = 0.f, cnt = 0.f;
    for (int b = threadIdx.x; b < NB; b += blockDim.x) {
        float mn = 2.f, mx = -2.f;
        #pragma unroll
        for (int l = 0; l < NL; l++) {
            mn = fminf(mn, g_mn[b * NL + l]);
            mx = fmaxf(mx, g_mx[b * NL + l]);
        }
        if (mn < 1.5f) {   // has_pos (any positive sim <= 1.0 < 1.5 < init 2.0)
            sum += fmaxf(mx - mn + 0.2f, 0.f);
            cnt += 1.f;
        }
    }
    #pragma unroll
    for (int o = 16; o > 0; o >>= 1) {
        sum += __shfl_xor_sync(0xffffffffu, sum, o);
        cnt += __shfl_xor_sync(0xffffffffu, cnt, o);
    }
    int w = threadIdx.x >> 5, lane = threadIdx.x & 31;
    if (lane == 0) { s_s[w] = sum; s_c[w] = cnt; }
    __syncthreads();
    if (w == 0) {
        sum = (lane < 32) ? s_s[lane] : 0.f;
        cnt = (lane < 32) ? s_c[lane] : 0.f;
        #pragma unroll
        for (int o = 16; o > 0; o >>= 1) {
            sum += __shfl_xor_sync(0xffffffffu, sum, o);
            cnt += __shfl_xor_sync(0xffffffffu, cnt, o);
        }
        if (lane == 0) out[0] = sum / fmaxf(cnt, 1.f);
    }
}

// ---------------------------------------------------------------------------
extern "C" void kernel_launch(void* const* d_in, const int* in_sizes, int n_in,
                              void* d_out, int out_size) {
    const float* anchors   = (const float*)d_in[0];   // [B, D]
    const float* centroids = (const float*)d_in[1];   // [L, C, D]
    const int*   clab      = (const int*)d_in[2];     // [L, C]
    const int*   lpe       = (const int*)d_in[3];     // [L, N]
    const int*   lidx      = (const int*)d_in[4];     // [B]

    normalize_rows_kernel<<<NB / 8, 256>>>(anchors, NB, 0);
    normalize_rows_kernel<<<(NL * NC) / 8, 256>>>(centroids, NL * NC, 1);

    dim3 grid(NB / BM, NL);
    simred_kernel<<<grid, 128>>>(clab, lpe, lidx);

    finalize_kernel<<<1, 1024>>>((float*)d_out);
}